// round 4
// baseline (speedup 1.0000x reference)
#include <cuda_runtime.h>
#include <math.h>
#include <stdint.h>

#define BATCH 4
#define SEQ   1024
#define QDIM  512
#define NH    8
#define HD    64
#define BH    (BATCH*NH)
#define OUT_ELEMS  (BATCH*SEQ*HD)
#define PROJ_ELEMS (BATCH*NH*SEQ*HD)
#define NROWS (BH*SEQ)            // 32768 attn rows
#define QCHUNKS 4

__device__ float g_q[PROJ_ELEMS];
__device__ float g_k[PROJ_ELEMS];
__device__ float g_v[PROJ_ELEMS];
__device__ float g_cpart[QCHUNKS*PROJ_ELEMS];   // per-qchunk partial contexts
__device__ float g_partial[NROWS * 8];
__device__ float g_rinv[NROWS];

// ---------------------------------------------------------------------------
// tf32 helpers
// ---------------------------------------------------------------------------
__device__ __forceinline__ uint32_t f2tf(float x){
    uint32_t r; asm("cvt.rna.tf32.f32 %0, %1;" : "=r"(r) : "f"(x)); return r;
}
__device__ __forceinline__ float tfr(float x){ return __uint_as_float(f2tf(x)); }
__device__ __forceinline__ void split_tf(float x, uint32_t& hi, uint32_t& lo){
    hi = f2tf(x);
    lo = f2tf(x - __uint_as_float(hi));
}
__device__ __forceinline__ void mma8(float c[4], const uint32_t a[4], const uint32_t b[2]){
    asm volatile("mma.sync.aligned.m16n8k8.row.col.f32.tf32.tf32.f32 "
        "{%0,%1,%2,%3},{%4,%5,%6,%7},{%8,%9},{%0,%1,%2,%3};"
        : "+f"(c[0]),"+f"(c[1]),"+f"(c[2]),"+f"(c[3])
        : "r"(a[0]),"r"(a[1]),"r"(a[2]),"r"(a[3]),"r"(b[0]),"r"(b[1]));
}

__device__ __forceinline__ void lda4(const float* S, int stride, int row0, int kc, float a[4]){
    int lane = threadIdx.x & 31; int gr = lane>>2, c = lane&3;
    const float* p = S + (row0+gr)*stride + kc + c;
    a[0]=p[0]; a[1]=p[8*stride]; a[2]=p[4]; a[3]=p[8*stride+4];
}
__device__ __forceinline__ void ldb2(const float* S, int stride, int n0, int kc, float b[2]){
    int lane = threadIdx.x & 31;
    const float* p = S + (n0+(lane>>2))*stride + kc + (lane&3);
    b[0]=p[0]; b[1]=p[4];
}
__device__ __forceinline__ void lda4u(const float* S, int stride, int row0, int kc, uint32_t a[4]){
    int lane = threadIdx.x & 31; int gr = lane>>2, c = lane&3;
    const float* p = S + (row0+gr)*stride + kc + c;
    a[0]=__float_as_uint(p[0]); a[1]=__float_as_uint(p[8*stride]);
    a[2]=__float_as_uint(p[4]); a[3]=__float_as_uint(p[8*stride+4]);
}
__device__ __forceinline__ void ldb2u(const float* S, int stride, int n0, int kc, uint32_t b[2]){
    int lane = threadIdx.x & 31;
    const float* p = S + (n0+(lane>>2))*stride + kc + (lane&3);
    b[0]=__float_as_uint(p[0]); b[1]=__float_as_uint(p[4]);
}
__device__ __forceinline__ void lda4T(const float* S, int stride, int row0, int kc, float a[4]){
    int lane = threadIdx.x & 31; int gr = lane>>2, c = lane&3;
    const float* p = S + (kc+c)*stride + row0 + gr;
    a[0]=p[0]; a[1]=p[8]; a[2]=p[4*stride]; a[3]=p[4*stride+8];
}
__device__ __forceinline__ void ldb2T(const float* S, int stride, int n0, int kc, float b[2]){
    int lane = threadIdx.x & 31;
    const float* p = S + (kc+(lane&3))*stride + n0 + (lane>>2);
    b[0]=p[0]; b[1]=p[4*stride];
}

// ---------------------------------------------------------------------------
// Kernel 1: all three projections  Y = X @ W^T + b  (3xTF32) -> [b,h,l,d]
// ---------------------------------------------------------------------------
__global__ __launch_bounds__(256) void proj_all_kernel(
        const float* __restrict__ x0, const float* __restrict__ x1, const float* __restrict__ x2,
        const float* __restrict__ w0, const float* __restrict__ w1, const float* __restrict__ w2,
        const float* __restrict__ b0, const float* __restrict__ b1, const float* __restrict__ b2){
    __shared__ float Xs[128][36];
    __shared__ float Ws[64][36];
    int sel = blockIdx.z;
    const float* X = sel==0 ? x0 : sel==1 ? x1 : x2;
    const float* W = sel==0 ? w0 : sel==1 ? w1 : w2;
    const float* bias = sel==0 ? b0 : sel==1 ? b1 : b2;
    float* dst = sel==0 ? g_q : sel==1 ? g_k : g_v;

    int tid = threadIdx.x;
    int h = blockIdx.x, n0 = h*64;
    int m0 = blockIdx.y*128;
    int w = tid>>5, wm = w>>1, wn = w&1;
    int lane = tid&31, gr = lane>>2, c2 = (lane&3)*2;

    float acc[2][4][4] = {};
    for (int k0=0; k0<QDIM; k0+=32){
        __syncthreads();
        #pragma unroll
        for (int i=0;i<4;i++){ int lin=tid+i*256; int r=lin>>3, cc=(lin&7)*4;
            *(float4*)&Xs[r][cc] = *(const float4*)(X + (size_t)(m0+r)*QDIM + k0 + cc); }
        #pragma unroll
        for (int i=0;i<2;i++){ int lin=tid+i*256; int r=lin>>3, cc=(lin&7)*4;
            *(float4*)&Ws[r][cc] = *(const float4*)(W + (size_t)(n0+r)*QDIM + k0 + cc); }
        __syncthreads();
        #pragma unroll
        for (int kc=0; kc<32; kc+=8){
            uint32_t ah[2][4], al[2][4];
            #pragma unroll
            for (int mi=0;mi<2;mi++){
                float af[4]; lda4(&Xs[0][0],36, wm*32+mi*16, kc, af);
                #pragma unroll
                for (int j=0;j<4;j++) split_tf(af[j], ah[mi][j], al[mi][j]);
            }
            #pragma unroll
            for (int ni=0;ni<4;ni++){
                float bf[2]; uint32_t bh_[2], bl_[2];
                ldb2(&Ws[0][0],36, wn*32+ni*8, kc, bf);
                split_tf(bf[0],bh_[0],bl_[0]); split_tf(bf[1],bh_[1],bl_[1]);
                #pragma unroll
                for (int mi=0;mi<2;mi++){
                    mma8(acc[mi][ni], ah[mi], bh_);
                    mma8(acc[mi][ni], ah[mi], bl_);
                    mma8(acc[mi][ni], al[mi], bh_);
                }
            }
        }
    }
    int b = m0>>10, l0 = m0&1023;
    float* base = dst + (size_t)(b*NH+h)*SEQ*HD;
    #pragma unroll
    for (int mi=0;mi<2;mi++)
    #pragma unroll
    for (int ni=0;ni<4;ni++){
        int row = l0 + wm*32 + mi*16 + gr;
        int col = wn*32 + ni*8 + c2;
        float2 bb = *(const float2*)(bias + n0 + col);
        float2 v0 = {acc[mi][ni][0]+bb.x, acc[mi][ni][1]+bb.y};
        float2 v1 = {acc[mi][ni][2]+bb.x, acc[mi][ni][3]+bb.y};
        *(float2*)(base + (size_t)row*HD + col) = v0;
        *(float2*)(base + (size_t)(row+8)*HD + col) = v1;
    }
}

// ---------------------------------------------------------------------------
// Kernel 2: P = exp(0.5 * Q K^T) (3xTF32) -> attn (unnormalized) + row partials
// grid (8 kb, 8 qb, 32 bh), 512 threads
// ---------------------------------------------------------------------------
__global__ __launch_bounds__(512) void scores_exp_kernel(float* __restrict__ attn){
    extern __shared__ float sm[];
    float* Qhi = sm;
    float* Qlo = sm + 128*36;
    float* Khi = sm + 2*128*36;
    float* Klo = sm + 3*128*36;
    float (*sums)[4] = (float(*)[4])(sm + 4*128*36);

    int tid = threadIdx.x;
    int kb = blockIdx.x, q0b = blockIdx.y*128, bh = blockIdx.z;
    int w = tid>>5, wq = w>>2, wk = w&3;
    int lane = tid&31, gr = lane>>2, c2 = (lane&3)*2;
    const float* Qg = g_q + (size_t)(bh*SEQ + q0b)*HD;
    const float* Kg = g_k + (size_t)(bh*SEQ + kb*128)*HD;

    float acc[2][4][4] = {};
    #pragma unroll
    for (int dt=0; dt<2; dt++){
        int d0 = dt*32;
        __syncthreads();
        #pragma unroll
        for (int i=0;i<2;i++){
            int idx = tid + i*512;
            int r = idx>>3, cc = (idx&7)*4;
            float4 xq = *(const float4*)(Qg + (size_t)r*HD + d0 + cc);
            float4 xk = *(const float4*)(Kg + (size_t)r*HD + d0 + cc);
            float4 h, l;
            h.x=tfr(xq.x); l.x=tfr(xq.x-h.x); h.y=tfr(xq.y); l.y=tfr(xq.y-h.y);
            h.z=tfr(xq.z); l.z=tfr(xq.z-h.z); h.w=tfr(xq.w); l.w=tfr(xq.w-h.w);
            *(float4*)(Qhi + r*36 + cc) = h;
            *(float4*)(Qlo + r*36 + cc) = l;
            h.x=tfr(xk.x); l.x=tfr(xk.x-h.x); h.y=tfr(xk.y); l.y=tfr(xk.y-h.y);
            h.z=tfr(xk.z); l.z=tfr(xk.z-h.z); h.w=tfr(xk.w); l.w=tfr(xk.w-h.w);
            *(float4*)(Khi + r*36 + cc) = h;
            *(float4*)(Klo + r*36 + cc) = l;
        }
        __syncthreads();
        #pragma unroll
        for (int kc=0; kc<32; kc+=8){
            uint32_t ah[2][4], al[2][4];
            #pragma unroll
            for (int mi=0;mi<2;mi++){
                lda4u(Qhi,36, wq*32+mi*16, kc, ah[mi]);
                lda4u(Qlo,36, wq*32+mi*16, kc, al[mi]);
            }
            #pragma unroll
            for (int ni=0;ni<4;ni++){
                uint32_t bh_[2], bl_[2];
                ldb2u(Khi,36, wk*32+ni*8, kc, bh_);
                ldb2u(Klo,36, wk*32+ni*8, kc, bl_);
                #pragma unroll
                for (int mi=0;mi<2;mi++){
                    mma8(acc[mi][ni], ah[mi], bh_);
                    mma8(acc[mi][ni], ah[mi], bl_);
                    mma8(acc[mi][ni], al[mi], bh_);
                }
            }
        }
    }

    float* Ab = attn + (size_t)bh*SEQ*SEQ;
    float rs[2][2] = {};
    #pragma unroll
    for (int mi=0;mi<2;mi++)
    #pragma unroll
    for (int ni=0;ni<4;ni++){
        float e0 = __expf(acc[mi][ni][0]*0.5f);
        float e1 = __expf(acc[mi][ni][1]*0.5f);
        float e2 = __expf(acc[mi][ni][2]*0.5f);
        float e3 = __expf(acc[mi][ni][3]*0.5f);
        int row = q0b + wq*32 + mi*16 + gr;
        int col = kb*128 + wk*32 + ni*8 + c2;
        float2 v0 = {e0, e1}, v1 = {e2, e3};
        *(float2*)(Ab + (size_t)row*SEQ + col) = v0;
        *(float2*)(Ab + (size_t)(row+8)*SEQ + col) = v1;
        rs[mi][0] += e0 + e1;
        rs[mi][1] += e2 + e3;
    }
    #pragma unroll
    for (int mi=0;mi<2;mi++)
    #pragma unroll
    for (int j=0;j<2;j++){
        float s = rs[mi][j];
        s += __shfl_xor_sync(0xffffffffu, s, 1);
        s += __shfl_xor_sync(0xffffffffu, s, 2);
        rs[mi][j] = s;
    }
    if ((lane&3)==0){
        #pragma unroll
        for (int mi=0;mi<2;mi++)
        #pragma unroll
        for (int j=0;j<2;j++)
            sums[wq*32 + mi*16 + gr + j*8][wk] = rs[mi][j];
    }
    __syncthreads();
    if (tid < 128){
        float t = sums[tid][0] + sums[tid][1] + sums[tid][2] + sums[tid][3];
        g_partial[(((size_t)bh*SEQ + q0b + tid)<<3) + kb] = t;
    }
}

// ---------------------------------------------------------------------------
// Kernel 3: row-sum reduce -> 1/S
// ---------------------------------------------------------------------------
__global__ __launch_bounds__(256) void rowsum_kernel(){
    int r = blockIdx.x*256 + threadIdx.x;
    const float* p = g_partial + ((size_t)r<<3);
    float s = ((p[0]+p[1])+(p[2]+p[3])) + ((p[4]+p[5])+(p[6]+p[7]));
    g_rinv[r] = 1.0f / s;
}

// ---------------------------------------------------------------------------
// Kernel 4: normalize attn in place + PARTIAL context over a 256-q chunk
// grid (8 n-tiles, 32 bh, 4 q-chunks), 256 threads
// ---------------------------------------------------------------------------
__global__ __launch_bounds__(256) void context_norm_kernel(float* __restrict__ attn){
    __shared__ float Vs[32][68];     // [q][d]
    __shared__ float As[32][132];    // [q][kpos] (normalized)
    int tid = threadIdx.x;
    int nb = blockIdx.x*128, bh = blockIdx.y, qc = blockIdx.z;
    int w = tid>>5, wm = w>>2, wn = w&3;
    int lane = tid&31, gr = lane>>2, c2 = (lane&3)*2;
    float* Ag = attn + (size_t)bh*SEQ*SEQ + nb;
    const float* Vg = g_v + (size_t)bh*SEQ*HD;
    const float* rinv = g_rinv + (size_t)bh*SEQ;

    float acc[2][4][4] = {};
    int qlo = qc*(SEQ/QCHUNKS), qhi_ = qlo + SEQ/QCHUNKS;
    for (int q0=qlo; q0<qhi_; q0+=32){
        __syncthreads();
        #pragma unroll
        for (int i=0;i<4;i++){
            int lin=tid+i*256; int r=lin>>5, cc=(lin&31)*4;
            float4 v = *(const float4*)(Ag + (size_t)(q0+r)*SEQ + cc);
            float inv = rinv[q0+r];
            v.x*=inv; v.y*=inv; v.z*=inv; v.w*=inv;
            *(float4*)&As[r][cc] = v;
            *(float4*)(Ag + (size_t)(q0+r)*SEQ + cc) = v;   // final attn
        }
        #pragma unroll
        for (int i=0;i<2;i++){ int lin=tid+i*256; int r=lin>>4, cc=(lin&15)*4;
            *(float4*)&Vs[r][cc] = *(const float4*)(Vg + (size_t)(q0+r)*HD + cc); }
        __syncthreads();
        #pragma unroll
        for (int kc=0; kc<32; kc+=8){
            uint32_t a_[2][4];
            #pragma unroll
            for (int mi=0;mi<2;mi++){
                float af[4]; lda4T(&Vs[0][0],68, wm*32+mi*16, kc, af);
                #pragma unroll
                for (int j=0;j<4;j++) a_[mi][j] = f2tf(af[j]);
            }
            #pragma unroll
            for (int ni=0;ni<4;ni++){
                float bf[2]; uint32_t b_[2];
                ldb2T(&As[0][0],132, wn*32+ni*8, kc, bf);
                b_[0]=f2tf(bf[0]); b_[1]=f2tf(bf[1]);
                #pragma unroll
                for (int mi=0;mi<2;mi++) mma8(acc[mi][ni], a_[mi], b_);
            }
        }
    }
    float* Cb = g_cpart + (size_t)qc*PROJ_ELEMS + (size_t)bh*SEQ*HD;
    #pragma unroll
    for (int mi=0;mi<2;mi++)
    #pragma unroll
    for (int ni=0;ni<4;ni++){
        int drow = wm*32 + mi*16 + gr;
        int col  = nb + wn*32 + ni*8 + c2;
        Cb[(size_t)col*HD + drow]        = acc[mi][ni][0];
        Cb[(size_t)(col+1)*HD + drow]    = acc[mi][ni][1];
        Cb[(size_t)col*HD + drow+8]      = acc[mi][ni][2];
        Cb[(size_t)(col+1)*HD + drow+8]  = acc[mi][ni][3];
    }
}

// ---------------------------------------------------------------------------
// Kernel 5: output = (sum of 4 ctx partials) @ wp^T + bp   (single tf32)
// ---------------------------------------------------------------------------
__global__ __launch_bounds__(256) void outproj_kernel(const float* __restrict__ W,
        const float* __restrict__ bias, float* __restrict__ out){
    __shared__ float Cs[128][36];
    __shared__ float Ws[64][36];
    int tid = threadIdx.x;
    int m0 = blockIdx.x*128;
    int b = m0>>10, l0 = m0&1023;
    int w = tid>>5, wm = w>>1, wn = w&1;
    int lane = tid&31, gr = lane>>2, c2 = (lane&3)*2;

    float acc[2][4][4] = {};
    for (int k0=0; k0<QDIM; k0+=32){
        int h = k0>>6, off = k0&63;
        const float* Cg = g_cpart + ((size_t)(b*NH+h)*SEQ + l0)*HD + off;
        __syncthreads();
        #pragma unroll
        for (int i=0;i<4;i++){
            int lin=tid+i*256; int r=lin>>3, cc=(lin&7)*4;
            size_t o = (size_t)r*HD + cc;
            float4 a0 = *(const float4*)(Cg + o);
            float4 a1 = *(const float4*)(Cg + (size_t)PROJ_ELEMS + o);
            float4 a2 = *(const float4*)(Cg + (size_t)2*PROJ_ELEMS + o);
            float4 a3 = *(const float4*)(Cg + (size_t)3*PROJ_ELEMS + o);
            float4 s;
            s.x = (a0.x+a1.x)+(a2.x+a3.x);
            s.y = (a0.y+a1.y)+(a2.y+a3.y);
            s.z = (a0.z+a1.z)+(a2.z+a3.z);
            s.w = (a0.w+a1.w)+(a2.w+a3.w);
            *(float4*)&Cs[r][cc] = s;
        }
        #pragma unroll
        for (int i=0;i<2;i++){ int lin=tid+i*256; int r=lin>>3, cc=(lin&7)*4;
            *(float4*)&Ws[r][cc] = *(const float4*)(W + (size_t)r*QDIM + k0 + cc); }
        __syncthreads();
        #pragma unroll
        for (int kc=0; kc<32; kc+=8){
            uint32_t a_[2][4];
            #pragma unroll
            for (int mi=0;mi<2;mi++){
                float af[4]; lda4(&Cs[0][0],36, wm*32+mi*16, kc, af);
                #pragma unroll
                for (int j=0;j<4;j++) a_[mi][j] = f2tf(af[j]);
            }
            #pragma unroll
            for (int ni=0;ni<4;ni++){
                float bf[2]; uint32_t b_[2];
                ldb2(&Ws[0][0],36, wn*32+ni*8, kc, bf);
                b_[0]=f2tf(bf[0]); b_[1]=f2tf(bf[1]);
                #pragma unroll
                for (int mi=0;mi<2;mi++) mma8(acc[mi][ni], a_[mi], b_);
            }
        }
    }
    #pragma unroll
    for (int mi=0;mi<2;mi++)
    #pragma unroll
    for (int ni=0;ni<4;ni++){
        int row = m0 + wm*32 + mi*16 + gr;
        int col = wn*32 + ni*8 + c2;
        float2 bb = *(const float2*)(bias + col);
        float2 v0 = {acc[mi][ni][0]+bb.x, acc[mi][ni][1]+bb.y};
        float2 v1 = {acc[mi][ni][2]+bb.x, acc[mi][ni][3]+bb.y};
        *(float2*)(out + (size_t)row*HD + col) = v0;
        *(float2*)(out + (size_t)(row+8)*HD + col) = v1;
    }
}

// ---------------------------------------------------------------------------
extern "C" void kernel_launch(void* const* d_in, const int* in_sizes, int n_in,
                              void* d_out, int out_size) {
    const float* q  = (const float*)d_in[0];
    const float* k  = (const float*)d_in[1];
    const float* v  = (const float*)d_in[2];
    const float* wq = (const float*)d_in[3];
    const float* bq = (const float*)d_in[4];
    const float* wk = (const float*)d_in[5];
    const float* bk = (const float*)d_in[6];
    const float* wv = (const float*)d_in[7];
    const float* bv = (const float*)d_in[8];
    const float* wp = (const float*)d_in[9];
    const float* bp = (const float*)d_in[10];

    float* out  = (float*)d_out;
    float* attn = out + OUT_ELEMS;

    static int smem_set = 0;
    const int SCORES_SMEM = (4*128*36 + 128*4) * 4;   // 75776 B
    if (!smem_set){
        cudaFuncSetAttribute(scores_exp_kernel,
            cudaFuncAttributeMaxDynamicSharedMemorySize, SCORES_SMEM);
        smem_set = 1;
    }

    dim3 projGrid(NH, (BATCH*SEQ)/128, 3);            // (8, 32, 3)
    proj_all_kernel<<<projGrid, 256>>>(q, k, v, wq, wk, wv, bq, bk, bv);

    dim3 scoreGrid(SEQ/128, SEQ/128, BH);             // (8, 8, 32)
    scores_exp_kernel<<<scoreGrid, 512, SCORES_SMEM>>>(attn);

    rowsum_kernel<<<NROWS/256, 256>>>();

    dim3 ctxGrid(SEQ/128, BH, QCHUNKS);               // (8, 32, 4)
    context_norm_kernel<<<ctxGrid, 256>>>(attn);

    outproj_kernel<<<(BATCH*SEQ)/128, 256>>>(wp, bp, out);
}

// round 5
// speedup vs baseline: 1.2326x; 1.2326x over previous
#include <cuda_runtime.h>
#include <cuda_bf16.h>
#include <math.h>
#include <stdint.h>

#define BATCH 4
#define SEQ   1024
#define QDIM  512
#define NH    8
#define HD    64
#define BH    (BATCH*NH)
#define OUT_ELEMS  (BATCH*SEQ*HD)
#define PROJ_ELEMS (BATCH*NH*SEQ*HD)
#define NROWS (BH*SEQ)
#define QCHUNKS 4

__device__ float g_q[PROJ_ELEMS];
__device__ float g_k[PROJ_ELEMS];
__device__ float g_v[PROJ_ELEMS];
__device__ float g_cpart[QCHUNKS*PROJ_ELEMS];
__device__ float g_partial[NROWS * 8];
__device__ float g_rinv[NROWS];

// ---------------------------------------------------------------------------
// bf16 split helpers
// ---------------------------------------------------------------------------
__device__ __forceinline__ uint32_t packbf(float x, float y){
    __nv_bfloat162 t = __floats2bfloat162_rn(x, y);
    return *(uint32_t*)&t;
}
// pair (x,y) -> hi plane (bf16x2) + lo plane (bf16x2 residual)
__device__ __forceinline__ void packsplit(float x, float y, uint32_t& hi, uint32_t& lo){
    __nv_bfloat16 xh = __float2bfloat16_rn(x);
    __nv_bfloat16 yh = __float2bfloat16_rn(y);
    __nv_bfloat162 h; h.x = xh; h.y = yh;
    hi = *(uint32_t*)&h;
    lo = packbf(x - __bfloat162float(xh), y - __bfloat162float(yh));
}
__device__ __forceinline__ void mmabf(float c[4], const uint32_t a[4], const uint32_t b[2]){
    asm volatile("mma.sync.aligned.m16n8k16.row.col.f32.bf16.bf16.f32 "
        "{%0,%1,%2,%3},{%4,%5,%6,%7},{%8,%9},{%0,%1,%2,%3};"
        : "+f"(c[0]),"+f"(c[1]),"+f"(c[2]),"+f"(c[3])
        : "r"(a[0]),"r"(a[1]),"r"(a[2]),"r"(a[3]),"r"(b[0]),"r"(b[1]));
}
// packed-smem fragment loads. S is uint32 (bf16x2 pairs along k), row-major,
// stride in packed units. kp = k16step*8.
__device__ __forceinline__ void ldA(const uint32_t* S, int str, int row0, int kp, uint32_t a[4]){
    int lane = threadIdx.x & 31; int gr = lane>>2, tc = lane&3;
    const uint32_t* p = S + (row0+gr)*str + kp + tc;
    a[0]=p[0]; a[1]=p[8*str]; a[2]=p[4]; a[3]=p[8*str+4];
}
__device__ __forceinline__ void ldB(const uint32_t* S, int str, int n0, int kp, uint32_t b[2]){
    int lane = threadIdx.x & 31;
    const uint32_t* p = S + (n0+(lane>>2))*str + kp + (lane&3);
    b[0]=p[0]; b[1]=p[4];
}

// ---------------------------------------------------------------------------
// Kernel 1: all three projections  Y = X @ W^T + b  (3-term bf16) -> [b,h,l,d]
// grid (8 heads, 32 m-tiles, 3 sel), 256 threads, tile 128m x 64n, warp 32x32
// ---------------------------------------------------------------------------
__global__ __launch_bounds__(256) void proj_all_kernel(
        const float* __restrict__ x0, const float* __restrict__ x1, const float* __restrict__ x2,
        const float* __restrict__ w0, const float* __restrict__ w1, const float* __restrict__ w2,
        const float* __restrict__ b0, const float* __restrict__ b1, const float* __restrict__ b2){
    __shared__ uint32_t Xhi[128*17], Xlo[128*17];
    __shared__ uint32_t Whi[64*17],  Wlo[64*17];
    int sel = blockIdx.z;
    const float* X = sel==0 ? x0 : sel==1 ? x1 : x2;
    const float* W = sel==0 ? w0 : sel==1 ? w1 : w2;
    const float* bias = sel==0 ? b0 : sel==1 ? b1 : b2;
    float* dst = sel==0 ? g_q : sel==1 ? g_k : g_v;

    int tid = threadIdx.x;
    int h = blockIdx.x, n0 = h*64;
    int m0 = blockIdx.y*128;
    int w = tid>>5, wm = w>>1, wn = w&1;
    int lane = tid&31, gr = lane>>2, c2 = (lane&3)*2;

    float acc[2][4][4] = {};
    for (int k0=0; k0<QDIM; k0+=32){
        __syncthreads();
        #pragma unroll
        for (int i=0;i<4;i++){
            int lin = tid + i*256;           // 1024 float4 groups (128x32)
            int r = lin>>3, c4 = lin&7;
            float4 xv = *(const float4*)(X + (size_t)(m0+r)*QDIM + k0 + c4*4);
            uint32_t h0,l0,h1,l1;
            packsplit(xv.x, xv.y, h0, l0);
            packsplit(xv.z, xv.w, h1, l1);
            Xhi[r*17 + c4*2]   = h0; Xhi[r*17 + c4*2+1] = h1;
            Xlo[r*17 + c4*2]   = l0; Xlo[r*17 + c4*2+1] = l1;
        }
        #pragma unroll
        for (int i=0;i<2;i++){
            int lin = tid + i*256;           // 512 float4 groups (64x32)
            int r = lin>>3, c4 = lin&7;
            float4 wv = *(const float4*)(W + (size_t)(n0+r)*QDIM + k0 + c4*4);
            uint32_t h0,l0,h1,l1;
            packsplit(wv.x, wv.y, h0, l0);
            packsplit(wv.z, wv.w, h1, l1);
            Whi[r*17 + c4*2]   = h0; Whi[r*17 + c4*2+1] = h1;
            Wlo[r*17 + c4*2]   = l0; Wlo[r*17 + c4*2+1] = l1;
        }
        __syncthreads();
        #pragma unroll
        for (int ks=0; ks<2; ks++){
            int kp = ks*8;
            uint32_t ah[2][4], al[2][4];
            #pragma unroll
            for (int mi=0;mi<2;mi++){
                ldA(Xhi,17, wm*32+mi*16, kp, ah[mi]);
                ldA(Xlo,17, wm*32+mi*16, kp, al[mi]);
            }
            #pragma unroll
            for (int ni=0;ni<4;ni++){
                uint32_t bh_[2], bl_[2];
                ldB(Whi,17, wn*32+ni*8, kp, bh_);
                ldB(Wlo,17, wn*32+ni*8, kp, bl_);
                #pragma unroll
                for (int mi=0;mi<2;mi++){
                    mmabf(acc[mi][ni], ah[mi], bh_);
                    mmabf(acc[mi][ni], ah[mi], bl_);
                    mmabf(acc[mi][ni], al[mi], bh_);
                }
            }
        }
    }
    int b = m0>>10, l0 = m0&1023;
    float* base = dst + (size_t)(b*NH+h)*SEQ*HD;
    #pragma unroll
    for (int mi=0;mi<2;mi++)
    #pragma unroll
    for (int ni=0;ni<4;ni++){
        int row = l0 + wm*32 + mi*16 + gr;
        int col = wn*32 + ni*8 + c2;
        float2 bb = *(const float2*)(bias + n0 + col);
        float2 v0 = {acc[mi][ni][0]+bb.x, acc[mi][ni][1]+bb.y};
        float2 v1 = {acc[mi][ni][2]+bb.x, acc[mi][ni][3]+bb.y};
        *(float2*)(base + (size_t)row*HD + col) = v0;
        *(float2*)(base + (size_t)(row+8)*HD + col) = v1;
    }
}

// ---------------------------------------------------------------------------
// Kernel 2: P = exp(0.5 * Q K^T) (3-term bf16) -> attn (unnormalized) + partials
// grid (8 kb, 8 qb, 32 bh), 512 threads, tile 128q x 128k, warp 32x32
// ---------------------------------------------------------------------------
__global__ __launch_bounds__(512) void scores_exp_kernel(float* __restrict__ attn){
    __shared__ uint32_t Qhi[128*17], Qlo[128*17];
    __shared__ uint32_t Khi[128*17], Klo[128*17];
    __shared__ float sums[128][4];

    int tid = threadIdx.x;
    int kb = blockIdx.x, q0b = blockIdx.y*128, bh = blockIdx.z;
    int w = tid>>5, wq = w>>2, wk = w&3;
    int lane = tid&31, gr = lane>>2, c2 = (lane&3)*2;
    const float* Qg = g_q + (size_t)(bh*SEQ + q0b)*HD;
    const float* Kg = g_k + (size_t)(bh*SEQ + kb*128)*HD;

    float acc[2][4][4] = {};
    #pragma unroll
    for (int dt=0; dt<2; dt++){
        int d0 = dt*32;
        __syncthreads();
        #pragma unroll
        for (int i=0;i<2;i++){
            int lin = tid + i*512;           // 1024 float4 groups
            int r = lin>>3, c4 = lin&7;
            float4 xq = *(const float4*)(Qg + (size_t)r*HD + d0 + c4*4);
            float4 xk = *(const float4*)(Kg + (size_t)r*HD + d0 + c4*4);
            uint32_t h0,l0,h1,l1;
            packsplit(xq.x, xq.y, h0, l0); packsplit(xq.z, xq.w, h1, l1);
            Qhi[r*17 + c4*2] = h0; Qhi[r*17 + c4*2+1] = h1;
            Qlo[r*17 + c4*2] = l0; Qlo[r*17 + c4*2+1] = l1;
            packsplit(xk.x, xk.y, h0, l0); packsplit(xk.z, xk.w, h1, l1);
            Khi[r*17 + c4*2] = h0; Khi[r*17 + c4*2+1] = h1;
            Klo[r*17 + c4*2] = l0; Klo[r*17 + c4*2+1] = l1;
        }
        __syncthreads();
        #pragma unroll
        for (int ks=0; ks<2; ks++){
            int kp = ks*8;
            uint32_t ah[2][4], al[2][4];
            #pragma unroll
            for (int mi=0;mi<2;mi++){
                ldA(Qhi,17, wq*32+mi*16, kp, ah[mi]);
                ldA(Qlo,17, wq*32+mi*16, kp, al[mi]);
            }
            #pragma unroll
            for (int ni=0;ni<4;ni++){
                uint32_t bh_[2], bl_[2];
                ldB(Khi,17, wk*32+ni*8, kp, bh_);
                ldB(Klo,17, wk*32+ni*8, kp, bl_);
                #pragma unroll
                for (int mi=0;mi<2;mi++){
                    mmabf(acc[mi][ni], ah[mi], bh_);
                    mmabf(acc[mi][ni], ah[mi], bl_);
                    mmabf(acc[mi][ni], al[mi], bh_);
                }
            }
        }
    }

    float* Ab = attn + (size_t)bh*SEQ*SEQ;
    float rs[2][2] = {};
    #pragma unroll
    for (int mi=0;mi<2;mi++)
    #pragma unroll
    for (int ni=0;ni<4;ni++){
        float e0 = __expf(acc[mi][ni][0]*0.5f);
        float e1 = __expf(acc[mi][ni][1]*0.5f);
        float e2 = __expf(acc[mi][ni][2]*0.5f);
        float e3 = __expf(acc[mi][ni][3]*0.5f);
        int row = q0b + wq*32 + mi*16 + gr;
        int col = kb*128 + wk*32 + ni*8 + c2;
        float2 v0 = {e0, e1}, v1 = {e2, e3};
        *(float2*)(Ab + (size_t)row*SEQ + col) = v0;
        *(float2*)(Ab + (size_t)(row+8)*SEQ + col) = v1;
        rs[mi][0] += e0 + e1;
        rs[mi][1] += e2 + e3;
    }
    #pragma unroll
    for (int mi=0;mi<2;mi++)
    #pragma unroll
    for (int j=0;j<2;j++){
        float s = rs[mi][j];
        s += __shfl_xor_sync(0xffffffffu, s, 1);
        s += __shfl_xor_sync(0xffffffffu, s, 2);
        rs[mi][j] = s;
    }
    if ((lane&3)==0){
        #pragma unroll
        for (int mi=0;mi<2;mi++)
        #pragma unroll
        for (int j=0;j<2;j++)
            sums[wq*32 + mi*16 + gr + j*8][wk] = rs[mi][j];
    }
    __syncthreads();
    if (tid < 128){
        float t = sums[tid][0] + sums[tid][1] + sums[tid][2] + sums[tid][3];
        g_partial[(((size_t)bh*SEQ + q0b + tid)<<3) + kb] = t;
    }
}

// ---------------------------------------------------------------------------
// Kernel 3: row-sum reduce -> 1/S
// ---------------------------------------------------------------------------
__global__ __launch_bounds__(256) void rowsum_kernel(){
    int r = blockIdx.x*256 + threadIdx.x;
    const float* p = g_partial + ((size_t)r<<3);
    float s = ((p[0]+p[1])+(p[2]+p[3])) + ((p[4]+p[5])+(p[6]+p[7]));
    g_rinv[r] = 1.0f / s;
}

// ---------------------------------------------------------------------------
// Kernel 4: normalize attn in place + PARTIAL context over a 256-q chunk
// (3-term bf16). grid (8 n-tiles, 32 bh, 4 q-chunks), 256 threads.
// M=64(d) x N=128(kpos), reduction q. 8 warps: wm(0..3 over m? no) ->
// warps: wm = w>>2 is wrong for 8 warps; use wm = w&3 over M? We have 8 warps:
// layout wm(4) x wn(2): warp tile m16 x n64 -> ni 0..7. Use wm=w>>1(4), wn=w&1.
// ---------------------------------------------------------------------------
__global__ __launch_bounds__(256) void context_norm_kernel(float* __restrict__ attn){
    __shared__ uint32_t Vhi[64*17], Vlo[64*17];
    __shared__ uint32_t Ahi[128*17], Alo[128*17];
    int tid = threadIdx.x;
    int nb = blockIdx.x*128, bh = blockIdx.y, qc = blockIdx.z;
    int w = tid>>5, wm = w>>1, wn = w&1;     // wm: 4 m16 tiles (d), wn: 2 halves of N
    int lane = tid&31, gr = lane>>2, tc = lane&3;
    float* Ag = attn + (size_t)bh*SEQ*SEQ + nb;
    const float* Vg = g_v + (size_t)bh*SEQ*HD;
    const float* rinv = g_rinv + (size_t)bh*SEQ;

    float acc[8][4] = {};   // 8 n8-tiles per warp (n64), m16
    int qlo = qc*(SEQ/QCHUNKS), qhi_ = qlo + SEQ/QCHUNKS;
    for (int q0=qlo; q0<qhi_; q0+=32){
        __syncthreads();
        // V tile 32q x 64d -> Vhi/Vlo packed [d][qp]
        #pragma unroll
        for (int i=0;i<4;i++){
            int p = tid + i*256;
            int d = p & 63, qp = p >> 6;
            float v0 = Vg[(size_t)(q0+2*qp)*HD + d];
            float v1 = Vg[(size_t)(q0+2*qp+1)*HD + d];
            uint32_t hh, ll; packsplit(v0, v1, hh, ll);
            Vhi[d*17+qp] = hh; Vlo[d*17+qp] = ll;
        }
        // A tile 32q x 128k: normalize, write back, pack transposed [kpos][qp]
        #pragma unroll
        for (int i=0;i<2;i++){
            int p = tid + i*256;
            int c4 = p & 31, qp = p >> 5;
            size_t o0 = (size_t)(q0+2*qp)*SEQ + c4*4;
            size_t o1 = o0 + SEQ;
            float4 a0 = *(const float4*)(Ag + o0);
            float4 a1 = *(const float4*)(Ag + o1);
            float i0 = rinv[q0+2*qp], i1 = rinv[q0+2*qp+1];
            a0.x*=i0; a0.y*=i0; a0.z*=i0; a0.w*=i0;
            a1.x*=i1; a1.y*=i1; a1.z*=i1; a1.w*=i1;
            *(float4*)(Ag + o0) = a0;
            *(float4*)(Ag + o1) = a1;
            uint32_t hh, ll;
            packsplit(a0.x, a1.x, hh, ll); Ahi[(c4*4+0)*17+qp]=hh; Alo[(c4*4+0)*17+qp]=ll;
            packsplit(a0.y, a1.y, hh, ll); Ahi[(c4*4+1)*17+qp]=hh; Alo[(c4*4+1)*17+qp]=ll;
            packsplit(a0.z, a1.z, hh, ll); Ahi[(c4*4+2)*17+qp]=hh; Alo[(c4*4+2)*17+qp]=ll;
            packsplit(a0.w, a1.w, hh, ll); Ahi[(c4*4+3)*17+qp]=hh; Alo[(c4*4+3)*17+qp]=ll;
        }
        __syncthreads();
        #pragma unroll
        for (int ks=0; ks<2; ks++){
            int kp = ks*8;
            uint32_t ah[4], al[4];
            ldA(Vhi,17, wm*16, kp, ah);
            ldA(Vlo,17, wm*16, kp, al);
            #pragma unroll
            for (int ni=0;ni<8;ni++){
                uint32_t bh_[2], bl_[2];
                ldB(Ahi,17, wn*64+ni*8, kp, bh_);
                ldB(Alo,17, wn*64+ni*8, kp, bl_);
                mmabf(acc[ni], ah, bh_);
                mmabf(acc[ni], ah, bl_);
                mmabf(acc[ni], al, bh_);
            }
        }
    }
    float* Cb = g_cpart + (size_t)qc*PROJ_ELEMS + (size_t)bh*SEQ*HD;
    #pragma unroll
    for (int ni=0;ni<8;ni++){
        int drow = wm*16 + gr;
        int col  = nb + wn*64 + ni*8 + tc*2;
        Cb[(size_t)col*HD + drow]         = acc[ni][0];
        Cb[(size_t)(col+1)*HD + drow]     = acc[ni][1];
        Cb[(size_t)col*HD + drow+8]       = acc[ni][2];
        Cb[(size_t)(col+1)*HD + drow+8]   = acc[ni][3];
    }
}

// ---------------------------------------------------------------------------
// Kernel 5: output = (sum of 4 ctx partials) @ wp^T + bp   (3-term bf16)
// ---------------------------------------------------------------------------
__global__ __launch_bounds__(256) void outproj_kernel(const float* __restrict__ W,
        const float* __restrict__ bias, float* __restrict__ out){
    __shared__ uint32_t Chi[128*17], Clo[128*17];
    __shared__ uint32_t Whi[64*17],  Wlo[64*17];
    int tid = threadIdx.x;
    int m0 = blockIdx.x*128;
    int b = m0>>10, l0 = m0&1023;
    int w = tid>>5, wm = w>>1, wn = w&1;
    int lane = tid&31, gr = lane>>2, c2 = (lane&3)*2;

    float acc[2][4][4] = {};
    for (int k0=0; k0<QDIM; k0+=32){
        int h = k0>>6, off = k0&63;
        const float* Cg = g_cpart + ((size_t)(b*NH+h)*SEQ + l0)*HD + off;
        __syncthreads();
        #pragma unroll
        for (int i=0;i<4;i++){
            int lin = tid + i*256;
            int r = lin>>3, c4 = lin&7;
            size_t o = (size_t)r*HD + c4*4;
            float4 a0 = *(const float4*)(Cg + o);
            float4 a1 = *(const float4*)(Cg + (size_t)PROJ_ELEMS + o);
            float4 a2 = *(const float4*)(Cg + (size_t)2*PROJ_ELEMS + o);
            float4 a3 = *(const float4*)(Cg + (size_t)3*PROJ_ELEMS + o);
            float4 s;
            s.x = (a0.x+a1.x)+(a2.x+a3.x);
            s.y = (a0.y+a1.y)+(a2.y+a3.y);
            s.z = (a0.z+a1.z)+(a2.z+a3.z);
            s.w = (a0.w+a1.w)+(a2.w+a3.w);
            uint32_t h0,l0_,h1,l1;
            packsplit(s.x, s.y, h0, l0_);
            packsplit(s.z, s.w, h1, l1);
            Chi[r*17 + c4*2] = h0; Chi[r*17 + c4*2+1] = h1;
            Clo[r*17 + c4*2] = l0_; Clo[r*17 + c4*2+1] = l1;
        }
        #pragma unroll
        for (int i=0;i<2;i++){
            int lin = tid + i*256;
            int r = lin>>3, c4 = lin&7;
            float4 wv = *(const float4*)(W + (size_t)r*QDIM + k0 + c4*4);
            uint32_t h0,l0_,h1,l1;
            packsplit(wv.x, wv.y, h0, l0_);
            packsplit(wv.z, wv.w, h1, l1);
            Whi[r*17 + c4*2] = h0; Whi[r*17 + c4*2+1] = h1;
            Wlo[r*17 + c4*2] = l0_; Wlo[r*17 + c4*2+1] = l1;
        }
        __syncthreads();
        #pragma unroll
        for (int ks=0; ks<2; ks++){
            int kp = ks*8;
            uint32_t ah[2][4], al[2][4];
            #pragma unroll
            for (int mi=0;mi<2;mi++){
                ldA(Chi,17, wm*32+mi*16, kp, ah[mi]);
                ldA(Clo,17, wm*32+mi*16, kp, al[mi]);
            }
            #pragma unroll
            for (int ni=0;ni<4;ni++){
                uint32_t bh_[2], bl_[2];
                ldB(Whi,17, wn*32+ni*8, kp, bh_);
                ldB(Wlo,17, wn*32+ni*8, kp, bl_);
                #pragma unroll
                for (int mi=0;mi<2;mi++){
                    mmabf(acc[mi][ni], ah[mi], bh_);
                    mmabf(acc[mi][ni], ah[mi], bl_);
                    mmabf(acc[mi][ni], al[mi], bh_);
                }
            }
        }
    }
    #pragma unroll
    for (int mi=0;mi<2;mi++)
    #pragma unroll
    for (int ni=0;ni<4;ni++){
        int row = m0 + wm*32 + mi*16 + gr;
        int col = wn*32 + ni*8 + c2;
        float2 bb = *(const float2*)(bias + col);
        float2 v0 = {acc[mi][ni][0]+bb.x, acc[mi][ni][1]+bb.y};
        float2 v1 = {acc[mi][ni][2]+bb.x, acc[mi][ni][3]+bb.y};
        *(float2*)(out + (size_t)row*HD + col) = v0;
        *(float2*)(out + (size_t)(row+8)*HD + col) = v1;
    }
}

// ---------------------------------------------------------------------------
extern "C" void kernel_launch(void* const* d_in, const int* in_sizes, int n_in,
                              void* d_out, int out_size) {
    const float* q  = (const float*)d_in[0];
    const float* k  = (const float*)d_in[1];
    const float* v  = (const float*)d_in[2];
    const float* wq = (const float*)d_in[3];
    const float* bq = (const float*)d_in[4];
    const float* wk = (const float*)d_in[5];
    const float* bk = (const float*)d_in[6];
    const float* wv = (const float*)d_in[7];
    const float* bv = (const float*)d_in[8];
    const float* wp = (const float*)d_in[9];
    const float* bp = (const float*)d_in[10];

    float* out  = (float*)d_out;
    float* attn = out + OUT_ELEMS;

    dim3 projGrid(NH, (BATCH*SEQ)/128, 3);            // (8, 32, 3)
    proj_all_kernel<<<projGrid, 256>>>(q, k, v, wq, wk, wv, bq, bk, bv);

    dim3 scoreGrid(SEQ/128, SEQ/128, BH);             // (8, 8, 32)
    scores_exp_kernel<<<scoreGrid, 512>>>(attn);

    rowsum_kernel<<<NROWS/256, 256>>>();

    dim3 ctxGrid(SEQ/128, BH, QCHUNKS);               // (8, 32, 4)
    context_norm_kernel<<<ctxGrid, 256>>>(attn);

    outproj_kernel<<<(BATCH*SEQ)/128, 256>>>(wp, bp, out);
}